// round 15
// baseline (speedup 1.0000x reference)
#include <cuda_runtime.h>
#include <cuda_fp16.h>
#include <cstdint>
#include <cstddef>

#define BB   8
#define NPTS 4096
#define SS   2048
#define KNB  64
#define CIN  64
#define HID  128
#define BSZ  (BB*SS)
#define R2F  0.04f
#define MAXC 1024
#define SROW 132              // fp32 staging row stride (64-row tile)

// ---------------- device scratch ----------------
__device__ float  g_ctr[BSZ*3];
__device__ int    g_nbr[BSZ*KNB];
__device__ int    g_cnt[BSZ];
__device__ float4 g_pos4[BB*NPTS];
__device__ uint2  g_H0h[(size_t)BSZ*2048];    // fp16 H0 (64x128 per block)
__device__ uint2  g_H1h[(size_t)BSZ*2048];    // fp16 H1
__device__ double g_stat[2][2][32][HID];      // 16384 doubles
__device__ float  g_scale[2][HID];
__device__ float  g_shift[2][HID];
// pair-fragment fp16 hi/lo weights: per slab 4096 u32 = [hi 2048 | lo 2048]
__device__ uint32_t g_WF0[3*4096];
__device__ uint32_t g_WF1[4*4096];
__device__ uint32_t g_WF2[4*4096];

// ---------------- helpers ----------------
__device__ __forceinline__ uint32_t smem_u32(const void* p) {
    uint32_t a;
    asm("{ .reg .u64 t; cvta.to.shared.u64 t, %1; cvt.u32.u64 %0, t; }" : "=r"(a) : "l"(p));
    return a;
}
__device__ __forceinline__ void cp16(void* dst, const void* src) {
    asm volatile("cp.async.ca.shared.global [%0], [%1], 16;"
                 :: "r"(smem_u32(dst)), "l"(src) : "memory");
}
#define CP_COMMIT() asm volatile("cp.async.commit_group;" ::: "memory")
#define CP_WAIT0()  asm volatile("cp.async.wait_group 0;" ::: "memory")

__device__ __forceinline__ uint32_t h2(float x, float y) {
    __half2 v = __floats2half2_rn(x, y);
    return *(uint32_t*)&v;
}

__device__ __forceinline__ void mma16(float* c, uint32_t a0, uint32_t a1, uint32_t a2,
                                      uint32_t a3, uint32_t b0, uint32_t b1) {
    asm volatile("mma.sync.aligned.m16n8k16.row.col.f32.f16.f16.f32 "
        "{%0,%1,%2,%3}, {%4,%5,%6,%7}, {%8,%9}, {%0,%1,%2,%3};\n"
        : "+f"(c[0]), "+f"(c[1]), "+f"(c[2]), "+f"(c[3])
        : "r"(a0), "r"(a1), "r"(a2), "r"(a3), "r"(b0), "r"(b1));
}

// M=64 GEMM slab: warp w owns rows 16w..16w+15. A' = fp16(A); B hi/lo images.
__device__ __forceinline__ void gemm_slab(const float* sA, const uint32_t* sB,
                                          float (*acc)[4], int w, int lane, int scol,
                                          int nkk) {
    int g = lane >> 2, tig = lane & 3;
#pragma unroll 1
    for (int kk = 0; kk < nkk; kk++) {
        const float* base = sA + (16*w + g)*SROW + scol + kk*16 + 2*tig;
        float2 v00 = *(const float2*)(base);
        float2 v01 = *(const float2*)(base + 8);
        float2 v10 = *(const float2*)(base + 8*SROW);
        float2 v11 = *(const float2*)(base + 8*SROW + 8);
        uint32_t a0 = h2(v00.x, v00.y);
        uint32_t a1 = h2(v10.x, v10.y);
        uint32_t a2 = h2(v01.x, v01.y);
        uint32_t a3 = h2(v11.x, v11.y);
        const uint32_t* bh = sB + kk*1024;
        const uint32_t* bl = sB + 2048 + kk*1024;
#pragma unroll
        for (int tth = 0; tth < 8; tth++) {
            uint4 b = *(const uint4*)&bh[(tth*32 + lane)*4];
            mma16(acc[2*tth],   a0, a1, a2, a3, b.x, b.y);
            mma16(acc[2*tth+1], a0, a1, a2, a3, b.z, b.w);
        }
#pragma unroll
        for (int tth = 0; tth < 8; tth++) {
            uint4 b = *(const uint4*)&bl[(tth*32 + lane)*4];
            mma16(acc[2*tth],   a0, a1, a2, a3, b.x, b.y);
            mma16(acc[2*tth+1], a0, a1, a2, a3, b.z, b.w);
        }
    }
}

// async B slab copy (each thread 8x uint4 = 16KB total)
__device__ __forceinline__ void stageB(uint32_t* buf, const uint32_t* src, int t) {
#pragma unroll
    for (int i = 0; i < 8; i++) {
        int idx = (t + i*128) * 4;
        cp16(buf + idx, src + idx);
    }
    CP_COMMIT();
}

// acc -> (+bias) -> staging rows (warp writes only its own 16 rows)
__device__ __forceinline__ void epi_to_stage(float* sA, float (*acc)[4], const float* bias,
                                             int w, int lane) {
    int g = lane >> 2, tig = lane & 3;
#pragma unroll
    for (int tt = 0; tt < 16; tt++) {
        int n0 = tt*8 + tig*2;
        float bz0 = bias[n0], bz1 = bias[n0+1];
        float* r0 = sA + (16*w + g)*SROW + n0;
        const float* a = acc[tt];
        *(float2*)r0            = make_float2(a[0]+bz0, a[1]+bz1);
        *(float2*)(r0 + 8*SROW) = make_float2(a[2]+bz0, a[3]+bz1);
    }
}

// staging (64x128) -> fp16 global H (2048 uint2)
__device__ __forceinline__ void stage_to_H(uint2* dstH, const float* sA, int t) {
    for (int i = t; i < 2048; i += 128) {
        const float* s = sA + (i >> 5)*SROW + (i & 31)*4;
        __half2 h0 = __floats2half2_rn(s[0], s[1]);
        __half2 h1 = __floats2half2_rn(s[2], s[3]);
        uint2 u;
        u.x = *(uint32_t*)&h0;
        u.y = *(uint32_t*)&h1;
        dstH[i] = u;
    }
}

// fp16 global H -> bn+relu -> fp32 staging (64x128)
__device__ __forceinline__ void H_to_stage(float* sA, const uint2* src, int t,
                                           const float* sc, const float* sh) {
    for (int i = t; i < 2048; i += 128) {
        int row = i >> 5, c4 = (i & 31) * 4;
        uint2 u = src[i];
        float2 f0 = __half22float2(*(__half2*)&u.x);
        float2 f1 = __half22float2(*(__half2*)&u.y);
        float4 z;
        z.x = fmaxf(0.f, fmaf(f0.x, sc[c4+0], sh[c4+0]));
        z.y = fmaxf(0.f, fmaf(f0.y, sc[c4+1], sh[c4+1]));
        z.z = fmaxf(0.f, fmaf(f1.x, sc[c4+2], sh[c4+2]));
        z.w = fmaxf(0.f, fmaf(f1.y, sc[c4+3], sh[c4+3]));
        *(float4*)(sA + row*SROW + c4) = z;
    }
}

// ---------------- weight fragment prep item (fp16 hi/lo, paired tt layout) ----------------
__device__ __forceinline__ void wprep_item(const float* __restrict__ W, int K,
                                           uint32_t* dst, int i) {
    int s = i >> 11, r = i & 2047;
    int q = r & 3, lane = (r >> 2) & 31, tth = (r >> 7) & 7, kk = (r >> 10) & 1;
    int reg = q & 1, tto = q >> 1;
    int tt = tth*2 + tto;
    int k0 = s*32 + kk*16 + reg*8 + (lane & 3)*2;
    int n  = tt*8 + (lane >> 2);
    float v0 = (k0     < K) ? W[k0*HID + n]     : 0.f;
    float v1 = (k0 + 1 < K) ? W[(k0+1)*HID + n] : 0.f;
    __half2 hh = __floats2half2_rn(v0, v1);
    float l0 = v0 - __half2float(__low2half(hh));
    float l1 = v1 - __half2float(__high2half(hh));
    dst[s*4096 + r]        = *(uint32_t*)&hh;
    dst[s*4096 + 2048 + r] = h2(l0, l1);
}

// ---------------- prep kernels (split so k_fps is launch #4 for ncu) ----------------
// pA: pos4 [0,32768) + zero ALL stats [32768,49152)
__global__ void k_pA(const float* __restrict__ pos) {
    int i = blockIdx.x * blockDim.x + threadIdx.x;
    if (i < 32768) {
        g_pos4[i] = make_float4(pos[3*i], pos[3*i+1], pos[3*i+2], 0.f);
    } else if (i < 49152) {
        (&g_stat[0][0][0][0])[i - 32768] = 0.0;
    }
}
// pB: W0 [0,6144) + W1 [6144,14336)
__global__ void k_pB(const float* __restrict__ W0, const float* __restrict__ W1) {
    int i = blockIdx.x * blockDim.x + threadIdx.x;
    if (i < 6144) wprep_item(W0, 67, g_WF0, i);
    else if (i < 14336) wprep_item(W1, HID, g_WF1, i - 6144);
}
// pC: W2 [0,8192)
__global__ void k_pC(const float* __restrict__ W2) {
    int i = blockIdx.x * blockDim.x + threadIdx.x;
    if (i < 8192) wprep_item(W2, HID, g_WF2, i);
}

// ---------------- farthest point sampling (1 sync/iter, smem coords) ----------------
__global__ void __launch_bounds__(1024) k_fps(const float* __restrict__ pos,
                                              float* __restrict__ octr,
                                              float* __restrict__ obat) {
    extern __shared__ float fs[];    // sx[4096], sy[4096], sz[4096]
    float* sx = fs;
    float* sy = fs + NPTS;
    float* sz = fs + 2*NPTS;
    int b = blockIdx.x, t = threadIdx.x;
    const float* p = pos + (size_t)b * NPTS * 3;
    float px[4], py[4], pz[4], md[4];
#pragma unroll
    for (int j = 0; j < 4; j++) {
        int i = t + j * 1024;
        px[j] = p[3*i]; py[j] = p[3*i+1]; pz[j] = p[3*i+2];
        sx[i] = px[j]; sy[i] = py[j]; sz[i] = pz[j];
        md[j] = __int_as_float(0x7f800000);
    }
    __shared__ unsigned svk[2][32];
    __shared__ unsigned svi[2][32];
    int lane = t & 31, w = t >> 5;
    int last = 0;
    __syncthreads();
    for (int s = 0; s < SS; s++) {
        float qx = sx[last], qy = sy[last], qz = sz[last];
        if (t == 0) {
            int o = b*SS + s;
            g_ctr[o*3] = qx; g_ctr[o*3+1] = qy; g_ctr[o*3+2] = qz;
            if (octr) { octr[o*3] = qx; octr[o*3+1] = qy; octr[o*3+2] = qz; }
            if (obat) obat[o] = (float)b;
        }
        float bv = -1.f; int bi = 0;
#pragma unroll
        for (int j = 0; j < 4; j++) {
            float dx = px[j]-qx, dy = py[j]-qy, dz = pz[j]-qz;
            float d = fmaf(dz, dz, fmaf(dy, dy, __fmul_rn(dx, dx)));
            md[j] = fminf(md[j], d);
            if (md[j] > bv) { bv = md[j]; bi = t + j*1024; }  // strict >: lowest idx wins
        }
        unsigned key  = __float_as_uint(bv);
        unsigned vmax = __reduce_max_sync(0xffffffffu, key);
        unsigned cand = (key == vmax) ? (unsigned)bi : 0xffffffffu;
        unsigned imin = __reduce_min_sync(0xffffffffu, cand);
        int buf = s & 1;
        if (lane == 0) { svk[buf][w] = vmax; svi[buf][w] = imin; }
        __syncthreads();
        unsigned k2 = svk[buf][lane], i2 = svi[buf][lane];
        unsigned vm2 = __reduce_max_sync(0xffffffffu, k2);
        unsigned c2  = (k2 == vm2) ? i2 : 0xffffffffu;
        last = (int)__reduce_min_sync(0xffffffffu, c2);
    }
}

// ---------------- radius-capped kNN (known-good) ----------------
__global__ void __launch_bounds__(128) k_nbr() {
    int c = blockIdx.x, t = threadIdx.x;
    int b = c >> 11;
    __shared__ float sd[MAXC];
    __shared__ int   sid[MAXC];
    __shared__ int   hist[128];
    __shared__ int   sc, so, s_tb, s_m, tc;
    __shared__ float td[256];
    __shared__ int   tdi[256];
    __shared__ int   wtot[4];
    if (t == 0) { sc = 0; so = 0; tc = 0; }
    hist[t] = 0;
    float cx = g_ctr[c*3], cy = g_ctr[c*3+1], cz = g_ctr[c*3+2];
    __syncthreads();
    for (int i = t; i < NPTS; i += 128) {
        float4 P = g_pos4[b*NPTS + i];
        float dx = P.x-cx, dy = P.y-cy, dz = P.z-cz;
        float d = fmaf(dz, dz, fmaf(dy, dy, __fmul_rn(dx, dx)));
        if (d <= R2F) {
            int k = atomicAdd(&sc, 1);
            if (k < MAXC) { sd[k] = d; sid[k] = i; }
        }
    }
    __syncthreads();
    int cnt = min(sc, MAXC);
    if (cnt <= KNB) {
        if (t < cnt) g_nbr[c*KNB + t] = sid[t];
        if (t == 0) g_cnt[c] = cnt;
        return;
    }
    const float bsc = 128.0f / R2F;
    for (int i = t; i < cnt; i += 128) {
        int bk = min(127, (int)(sd[i] * bsc));
        atomicAdd(&hist[bk], 1);
    }
    __syncthreads();
    {
        int lane = t & 31, w = t >> 5;
        int h = hist[t], v = h;
#pragma unroll
        for (int o = 1; o < 32; o <<= 1) {
            int u = __shfl_up_sync(0xffffffffu, v, o);
            if (lane >= o) v += u;
        }
        if (lane == 31) wtot[w] = v;
        __syncthreads();
        int base = 0;
        for (int k2 = 0; k2 < w; k2++) base += wtot[k2];
        int incl = v + base, excl = incl - h;
        if (incl >= KNB && excl < KNB) { s_tb = t; s_m = excl; }
    }
    __syncthreads();
    int tb = s_tb, m = s_m;
    for (int i = t; i < cnt; i += 128) {
        int bk = min(127, (int)(sd[i] * bsc));
        if (bk < tb) {
            int k = atomicAdd(&so, 1);
            g_nbr[c*KNB + k] = sid[i];
        } else if (bk == tb) {
            int k = atomicAdd(&tc, 1);
            if (k < 256) { td[k] = sd[i]; tdi[k] = sid[i]; }
        }
    }
    __syncthreads();
    int bn = min(tc, 256), rem = KNB - m;
    for (int i = t; i < bn; i += 128) {
        float di = td[i]; int ii = tdi[i];
        int rank = 0;
        for (int j2 = 0; j2 < bn; j2++) {
            float dj = td[j2]; int ij = tdi[j2];
            if (dj < di || (dj == di && ij < ii)) rank++;
        }
        if (rank < rem) {
            int k = atomicAdd(&so, 1);
            g_nbr[c*KNB + k] = tdi[i];
        }
    }
    if (t == 0) g_cnt[c] = KNB;
}

// ---------------- layer 0: gather -> GEMM (M=64) -> H0(fp16) + stats ----------------
__global__ void __launch_bounds__(128, 3) k_l0(const float* __restrict__ x,
                                               const float* __restrict__ b0) {
    extern __shared__ float sm[];
    float*    sA   = sm;                        // 64*132 f32
    uint32_t* sB0  = (uint32_t*)(sm + 64*SROW); // 4096 u32
    uint32_t* sB1  = sB0 + 4096;
    float*    bias = sm + 64*SROW + 8192;       // 128
    int t = threadIdx.x, w = t >> 5, lane = t & 31, blk = blockIdx.x;
    bias[t] = b0[t];

    stageB(sB0, g_WF0, t);   // slab 0 in flight

    // gather: 2 threads per row; h half of feature cols
    int e = t >> 1, h = t & 1;
    int cnt = g_cnt[blk];
    float* row = sA + e*SROW;
    float4 z4 = make_float4(0.f, 0.f, 0.f, 0.f);
    if (e < cnt) {
        int j = g_nbr[blk*KNB + e];
        int bcl = blk >> 11;
        const float4* xr = (const float4*)(x + (size_t)(bcl*NPTS + j)*CIN) + h*8;
#pragma unroll
        for (int q = 0; q < 8; q++)
            *(float4*)(row + h*32 + 4*q) = xr[q];
        if (h == 0) {
            float4 P = g_pos4[bcl*NPTS + j];
            row[64] = P.x - g_ctr[blk*3];
            row[65] = P.y - g_ctr[blk*3+1];
            row[66] = P.z - g_ctr[blk*3+2];
            row[67] = 0.f;
            *(float4*)(row + 68) = z4;
            *(float4*)(row + 72) = z4;
            *(float4*)(row + 76) = z4;
        }
    } else {
#pragma unroll
        for (int q = 0; q < 8; q++)
            *(float4*)(row + h*32 + 4*q) = z4;
        if (h == 0) {
            *(float4*)(row + 64) = z4;
            *(float4*)(row + 68) = z4;
            *(float4*)(row + 72) = z4;
            *(float4*)(row + 76) = z4;
        }
    }

    float acc[16][4];
#pragma unroll
    for (int i = 0; i < 16; i++)
#pragma unroll
        for (int r = 0; r < 4; r++) acc[i][r] = 0.f;

    uint32_t* bufs[2] = { sB0, sB1 };
#pragma unroll 1
    for (int s = 0; s < 3; s++) {
        CP_WAIT0();
        __syncthreads();
        if (s + 1 < 3) stageB(bufs[(s+1)&1], g_WF0 + (s+1)*4096, t);
        gemm_slab(sA, bufs[s&1], acc, w, lane, s*32, (s < 2) ? 2 : 1);
    }

    epi_to_stage(sA, acc, bias, w, lane);
    __syncthreads();

    stage_to_H(g_H0h + (size_t)blk * 2048, sA, t);

    float ssum = 0.f, ssq = 0.f;
    for (int r = 0; r < 64; r++) {
        if (r < cnt) {
            float v = sA[r*SROW + t];
            ssum += v; ssq = fmaf(v, v, ssq);
        }
    }
    atomicAdd(&g_stat[0][0][blk & 31][t], (double)ssum);
    atomicAdd(&g_stat[0][1][blk & 31][t], (double)ssq);
}

// ---------------- bn prepare ----------------
__global__ void k_prep(const float* __restrict__ gamma,
                       const float* __restrict__ beta, int layer) {
    int t = threadIdx.x;
    int local = 0;
    for (int i = t; i < BSZ; i += 128) local += g_cnt[i];
    __shared__ int sred[4];
    int lane = t & 31, w = t >> 5;
#pragma unroll
    for (int off = 16; off > 0; off >>= 1)
        local += __shfl_down_sync(0xffffffffu, local, off);
    if (lane == 0) sred[w] = local;
    __syncthreads();
    double cntd = (double)(sred[0] + sred[1] + sred[2] + sred[3]);
    double s = 0.0, q = 0.0;
    for (int k = 0; k < 32; k++) {
        s += g_stat[layer][0][k][t];
        q += g_stat[layer][1][k][t];
    }
    double mean = s / cntd;
    double var = q / cntd - mean * mean;
    if (var < 0.0) var = 0.0;
    double a = (double)gamma[t] * rsqrt(var + 1e-5);
    g_scale[layer][t] = (float)a;
    g_shift[layer][t] = (float)((double)beta[t] - mean * a);
}

// ---------------- layer 1: bnrelu(H0) -> GEMM (M=64) -> H1(fp16) + stats ----------------
__global__ void __launch_bounds__(128, 3) k_l1(const float* __restrict__ b1) {
    extern __shared__ float sm[];
    float*    sA   = sm;
    uint32_t* sB0  = (uint32_t*)(sm + 64*SROW);
    uint32_t* sB1  = sB0 + 4096;
    float*    bias = sm + 64*SROW + 8192;
    float*    sc   = bias + 128;
    float*    sh   = sc + 128;
    int t = threadIdx.x, w = t >> 5, lane = t & 31, blk = blockIdx.x;
    bias[t] = b1[t]; sc[t] = g_scale[0][t]; sh[t] = g_shift[0][t];

    stageB(sB0, g_WF1, t);
    __syncthreads();   // sc/sh visible for staging below

    H_to_stage(sA, g_H0h + (size_t)blk * 2048, t, sc, sh);

    float acc[16][4];
#pragma unroll
    for (int i = 0; i < 16; i++)
#pragma unroll
        for (int r = 0; r < 4; r++) acc[i][r] = 0.f;

    uint32_t* bufs[2] = { sB0, sB1 };
#pragma unroll 1
    for (int s = 0; s < 4; s++) {
        CP_WAIT0();
        __syncthreads();
        if (s + 1 < 4) stageB(bufs[(s+1)&1], g_WF1 + (s+1)*4096, t);
        gemm_slab(sA, bufs[s&1], acc, w, lane, s*32, 2);
    }

    epi_to_stage(sA, acc, bias, w, lane);
    __syncthreads();

    stage_to_H(g_H1h + (size_t)blk * 2048, sA, t);

    int cnt = g_cnt[blk];
    float ssum = 0.f, ssq = 0.f;
    for (int r = 0; r < 64; r++) {
        if (r < cnt) {
            float v = sA[r*SROW + t];
            ssum += v; ssq = fmaf(v, v, ssq);
        }
    }
    atomicAdd(&g_stat[1][0][blk & 31][t], (double)ssum);
    atomicAdd(&g_stat[1][1][blk & 31][t], (double)ssq);
}

// ---------------- layer 2: bnrelu(H1) -> GEMM (M=64) -> masked max -> out ----------------
__global__ void __launch_bounds__(128, 3) k_l2(const float* __restrict__ b2,
                                               float* __restrict__ outp) {
    extern __shared__ float sm[];
    float*    sA   = sm;
    uint32_t* sB0  = (uint32_t*)(sm + 64*SROW);
    uint32_t* sB1  = sB0 + 4096;
    float*    bias = sm + 64*SROW + 8192;
    float*    sc   = bias + 128;
    float*    sh   = sc + 128;
    int t = threadIdx.x, w = t >> 5, lane = t & 31, blk = blockIdx.x;
    bias[t] = b2[t]; sc[t] = g_scale[1][t]; sh[t] = g_shift[1][t];

    stageB(sB0, g_WF2, t);
    __syncthreads();

    H_to_stage(sA, g_H1h + (size_t)blk * 2048, t, sc, sh);

    float acc[16][4];
#pragma unroll
    for (int i = 0; i < 16; i++)
#pragma unroll
        for (int r = 0; r < 4; r++) acc[i][r] = 0.f;

    uint32_t* bufs[2] = { sB0, sB1 };
#pragma unroll 1
    for (int s = 0; s < 4; s++) {
        CP_WAIT0();
        __syncthreads();
        if (s + 1 < 4) stageB(bufs[(s+1)&1], g_WF2 + (s+1)*4096, t);
        gemm_slab(sA, bufs[s&1], acc, w, lane, s*32, 2);
    }

    epi_to_stage(sA, acc, bias, w, lane);
    __syncthreads();

    int cnt = g_cnt[blk];
    const float NINF = __int_as_float(0xff800000);
    float m0 = NINF;
    for (int r = 0; r < 64; r++)
        if (r < cnt) m0 = fmaxf(m0, sA[r*SROW + t]);
    outp[(size_t)blk * HID + t] = m0;
}

// ---------------- launch ----------------
extern "C" void kernel_launch(void* const* d_in, const int* in_sizes, int n_in,
                              void* d_out, int out_size) {
    const float* x   = (const float*)d_in[0];
    const float* pos = (const float*)d_in[1];
    const float* W0  = (const float*)d_in[3];
    const float* b0  = (const float*)d_in[4];
    const float* g0  = (const float*)d_in[5];
    const float* be0 = (const float*)d_in[6];
    const float* W1  = (const float*)d_in[7];
    const float* b1  = (const float*)d_in[8];
    const float* g1  = (const float*)d_in[9];
    const float* be1 = (const float*)d_in[10];
    const float* W2  = (const float*)d_in[11];
    const float* b2  = (const float*)d_in[12];
    float* out = (float*)d_out;

    float* octr = (out_size >= BSZ*HID + BSZ*3) ? out + (size_t)BSZ*HID : nullptr;
    float* obat = (out_size >= BSZ*HID + BSZ*3 + BSZ) ? out + (size_t)BSZ*131 : nullptr;

    int smB = (64*SROW + 8192 + 384) * 4;    // 68,096 B -> 3 CTAs/SM
    int smF = 3 * NPTS * 4;                  // 49,152 B
    cudaFuncSetAttribute(k_l0, cudaFuncAttributeMaxDynamicSharedMemorySize, smB);
    cudaFuncSetAttribute(k_l1, cudaFuncAttributeMaxDynamicSharedMemorySize, smB);
    cudaFuncSetAttribute(k_l2, cudaFuncAttributeMaxDynamicSharedMemorySize, smB);
    cudaFuncSetAttribute(k_fps, cudaFuncAttributeMaxDynamicSharedMemorySize, smF);

    // launch order: k_fps is launch #4 (= ncu capture slot with the 2 harness launches)
    k_pA<<<(49152 + 255)/256, 256>>>(pos);
    k_pB<<<(14336 + 255)/256, 256>>>(W0, W1);
    k_pC<<<(8192 + 255)/256, 256>>>(W2);
    k_fps<<<BB, 1024, smF>>>(pos, octr, obat);
    k_nbr<<<BSZ, 128>>>();
    k_l0<<<BSZ, 128, smB>>>(x, b0);
    k_prep<<<1, 128>>>(g0, be0, 0);
    k_l1<<<BSZ, 128, smB>>>(b1);
    k_prep<<<1, 128>>>(g1, be1, 1);
    k_l2<<<BSZ, 128, smB>>>(b2, out);
}

// round 16
// speedup vs baseline: 1.0935x; 1.0935x over previous
#include <cuda_runtime.h>
#include <cuda_fp16.h>
#include <cstdint>
#include <cstddef>

#define BB   8
#define NPTS 4096
#define SS   2048
#define KNB  64
#define CIN  64
#define HID  128
#define BSZ  (BB*SS)
#define R2F  0.04f
#define MAXC 1024
#define NBLK (BSZ/2)          // 2 centroids per GEMM block
#define SROW 132              // fp32 staging row stride

// ---------------- device scratch ----------------
__device__ float  g_ctr[BSZ*3];
__device__ int    g_cnt[BSZ];
__device__ int    g_prog[BB];                 // fps progress per cloud
__device__ float4 g_pos4[BB*NPTS];
__device__ uint2  g_H0h[(size_t)NBLK*4096];   // fp16 H0
__device__ uint2  g_H1h[(size_t)NBLK*4096];   // fp16 H1
__device__ double g_stat[2][2][32][HID];      // 16384 doubles
__device__ float  g_scale[2][HID];
__device__ float  g_shift[2][HID];
// pair-fragment fp16 hi/lo weights: per slab 4096 u32 = [hi 2048 | lo 2048]
__device__ uint32_t g_WF0[3*4096];
__device__ uint32_t g_WF1[4*4096];
__device__ uint32_t g_WF2[4*4096];

// ---------------- helpers ----------------
__device__ __forceinline__ uint32_t smem_u32(const void* p) {
    uint32_t a;
    asm("{ .reg .u64 t; cvta.to.shared.u64 t, %1; cvt.u32.u64 %0, t; }" : "=r"(a) : "l"(p));
    return a;
}
__device__ __forceinline__ void cp16(void* dst, const void* src) {
    asm volatile("cp.async.ca.shared.global [%0], [%1], 16;"
                 :: "r"(smem_u32(dst)), "l"(src) : "memory");
}
#define CP_COMMIT() asm volatile("cp.async.commit_group;" ::: "memory")
#define CP_WAIT0()  asm volatile("cp.async.wait_group 0;" ::: "memory")

__device__ __forceinline__ uint32_t h2(float x, float y) {
    __half2 v = __floats2half2_rn(x, y);
    return *(uint32_t*)&v;
}

__device__ __forceinline__ void mma16(float* c, uint32_t a0, uint32_t a1, uint32_t a2,
                                      uint32_t a3, uint32_t b0, uint32_t b1) {
    asm volatile("mma.sync.aligned.m16n8k16.row.col.f32.f16.f16.f32 "
        "{%0,%1,%2,%3}, {%4,%5,%6,%7}, {%8,%9}, {%0,%1,%2,%3};\n"
        : "+f"(c[0]), "+f"(c[1]), "+f"(c[2]), "+f"(c[3])
        : "r"(a0), "r"(a1), "r"(a2), "r"(a3), "r"(b0), "r"(b1));
}

// M=128 GEMM slab (R14 config): A' = fp16(A); B pair-fragment hi/lo images.
__device__ __forceinline__ void gemm_slab(const float* sA, const uint32_t* sB,
                                          float (*acc)[4], int w, int lane, int scol,
                                          int nkk) {
    int g = lane >> 2, tig = lane & 3;
#pragma unroll 1
    for (int kk = 0; kk < nkk; kk++) {
        uint32_t a[2][4];
#pragma unroll
        for (int rt = 0; rt < 2; rt++) {
            const float* base = sA + (32*w + 16*rt + g)*SROW + scol + kk*16 + 2*tig;
            float2 v00 = *(const float2*)(base);
            float2 v01 = *(const float2*)(base + 8);
            float2 v10 = *(const float2*)(base + 8*SROW);
            float2 v11 = *(const float2*)(base + 8*SROW + 8);
            a[rt][0] = h2(v00.x, v00.y);
            a[rt][1] = h2(v10.x, v10.y);
            a[rt][2] = h2(v01.x, v01.y);
            a[rt][3] = h2(v11.x, v11.y);
        }
        const uint32_t* bh = sB + kk*1024;
        const uint32_t* bl = sB + 2048 + kk*1024;
#pragma unroll
        for (int tth = 0; tth < 8; tth++) {
            uint4 b = *(const uint4*)&bh[(tth*32 + lane)*4];
            mma16(acc[2*tth],      a[0][0], a[0][1], a[0][2], a[0][3], b.x, b.y);
            mma16(acc[16+2*tth],   a[1][0], a[1][1], a[1][2], a[1][3], b.x, b.y);
            mma16(acc[2*tth+1],    a[0][0], a[0][1], a[0][2], a[0][3], b.z, b.w);
            mma16(acc[16+2*tth+1], a[1][0], a[1][1], a[1][2], a[1][3], b.z, b.w);
        }
#pragma unroll
        for (int tth = 0; tth < 8; tth++) {
            uint4 b = *(const uint4*)&bl[(tth*32 + lane)*4];
            mma16(acc[2*tth],      a[0][0], a[0][1], a[0][2], a[0][3], b.x, b.y);
            mma16(acc[16+2*tth],   a[1][0], a[1][1], a[1][2], a[1][3], b.x, b.y);
            mma16(acc[2*tth+1],    a[0][0], a[0][1], a[0][2], a[0][3], b.z, b.w);
            mma16(acc[16+2*tth+1], a[1][0], a[1][1], a[1][2], a[1][3], b.z, b.w);
        }
    }
}

__device__ __forceinline__ void stageB(uint32_t* buf, const uint32_t* src, int t) {
#pragma unroll
    for (int i = 0; i < 8; i++) {
        int idx = (t + i*128) * 4;
        cp16(buf + idx, src + idx);
    }
    CP_COMMIT();
}

__device__ __forceinline__ void epi_to_stage(float* sA, float (*acc)[4], const float* bias,
                                             int w, int lane) {
    int g = lane >> 2, tig = lane & 3;
#pragma unroll
    for (int rt = 0; rt < 2; rt++)
#pragma unroll
        for (int tt = 0; tt < 16; tt++) {
            int n0 = tt*8 + tig*2;
            float bz0 = bias[n0], bz1 = bias[n0+1];
            float* r0 = sA + (32*w + 16*rt + g)*SROW + n0;
            const float* a = acc[rt*16 + tt];
            *(float2*)r0            = make_float2(a[0]+bz0, a[1]+bz1);
            *(float2*)(r0 + 8*SROW) = make_float2(a[2]+bz0, a[3]+bz1);
        }
}

__device__ __forceinline__ void stage_to_H(uint2* dstH, const float* sA, int t) {
    for (int i = t; i < 4096; i += 128) {
        const float* s = sA + (i >> 5)*SROW + (i & 31)*4;
        __half2 h0 = __floats2half2_rn(s[0], s[1]);
        __half2 h1 = __floats2half2_rn(s[2], s[3]);
        uint2 u;
        u.x = *(uint32_t*)&h0;
        u.y = *(uint32_t*)&h1;
        dstH[i] = u;
    }
}

__device__ __forceinline__ void H_to_stage(float* sA, const uint2* src, int t,
                                           const float* sc, const float* sh) {
    for (int i = t; i < 4096; i += 128) {
        int row = i >> 5, c4 = (i & 31) * 4;
        uint2 u = src[i];
        float2 f0 = __half22float2(*(__half2*)&u.x);
        float2 f1 = __half22float2(*(__half2*)&u.y);
        float4 z;
        z.x = fmaxf(0.f, fmaf(f0.x, sc[c4+0], sh[c4+0]));
        z.y = fmaxf(0.f, fmaf(f0.y, sc[c4+1], sh[c4+1]));
        z.z = fmaxf(0.f, fmaf(f1.x, sc[c4+2], sh[c4+2]));
        z.w = fmaxf(0.f, fmaf(f1.y, sc[c4+3], sh[c4+3]));
        *(float4*)(sA + row*SROW + c4) = z;
    }
}

// ---------------- weight fragment prep ----------------
__device__ __forceinline__ void wprep_item(const float* __restrict__ W, int K,
                                           uint32_t* dst, int i) {
    int s = i >> 11, r = i & 2047;
    int q = r & 3, lane = (r >> 2) & 31, tth = (r >> 7) & 7, kk = (r >> 10) & 1;
    int reg = q & 1, tto = q >> 1;
    int tt = tth*2 + tto;
    int k0 = s*32 + kk*16 + reg*8 + (lane & 3)*2;
    int n  = tt*8 + (lane >> 2);
    float v0 = (k0     < K) ? W[k0*HID + n]     : 0.f;
    float v1 = (k0 + 1 < K) ? W[(k0+1)*HID + n] : 0.f;
    __half2 hh = __floats2half2_rn(v0, v1);
    float l0 = v0 - __half2float(__low2half(hh));
    float l1 = v1 - __half2float(__high2half(hh));
    dst[s*4096 + r]        = *(uint32_t*)&hh;
    dst[s*4096 + 2048 + r] = h2(l0, l1);
}

// pA: pos4 [0,32768) + zero stats [32768,49152) + zero prog [49152,49160)
__global__ void k_pA(const float* __restrict__ pos) {
    int i = blockIdx.x * blockDim.x + threadIdx.x;
    if (i < 32768) {
        g_pos4[i] = make_float4(pos[3*i], pos[3*i+1], pos[3*i+2], 0.f);
    } else if (i < 49152) {
        (&g_stat[0][0][0][0])[i - 32768] = 0.0;
    } else if (i < 49160) {
        g_prog[i - 49152] = 0;
    }
}
__global__ void k_pB(const float* __restrict__ W0, const float* __restrict__ W1) {
    int i = blockIdx.x * blockDim.x + threadIdx.x;
    if (i < 6144) wprep_item(W0, 67, g_WF0, i);
    else if (i < 14336) wprep_item(W1, HID, g_WF1, i - 6144);
}
__global__ void k_pC(const float* __restrict__ W2) {
    int i = blockIdx.x * blockDim.x + threadIdx.x;
    if (i < 8192) wprep_item(W2, HID, g_WF2, i);
}

// ================= fused kernel: fps(8 blocks) || [nbr+gather+GEMM l0] =================

// --- fps role: 128 threads, 32 points/thread, coords in smem ---
__device__ void fps_role(float* sm, int b, int t,
                         float* __restrict__ octr, float* __restrict__ obat) {
    float* sx = sm;
    float* sy = sm + NPTS;
    float* sz = sm + 2*NPTS;
    unsigned* svk = (unsigned*)(sm + 3*NPTS);       // [2][4]
    unsigned* svi = (unsigned*)(sm + 3*NPTS + 8);   // [2][4]
    for (int i = t; i < NPTS; i += 128) {
        float4 P = g_pos4[b*NPTS + i];
        sx[i] = P.x; sy[i] = P.y; sz[i] = P.z;
    }
    float md[32];
#pragma unroll
    for (int j = 0; j < 32; j++) md[j] = __int_as_float(0x7f800000);
    int lane = t & 31, w = t >> 5;
    int last = 0;
    __syncthreads();
    for (int s = 0; s < SS; s++) {
        float qx = sx[last], qy = sy[last], qz = sz[last];
        if (t == 0) {
            int o = b*SS + s;
            g_ctr[o*3] = qx; g_ctr[o*3+1] = qy; g_ctr[o*3+2] = qz;
            if (octr) { octr[o*3] = qx; octr[o*3+1] = qy; octr[o*3+2] = qz; }
            if (obat) obat[o] = (float)b;
        }
        float bv = -1.f; int bi = 0;
#pragma unroll
        for (int j = 0; j < 32; j++) {
            int i = t + j*128;
            float dx = sx[i]-qx, dy = sy[i]-qy, dz = sz[i]-qz;
            float d = fmaf(dz, dz, fmaf(dy, dy, __fmul_rn(dx, dx)));
            md[j] = fminf(md[j], d);
            if (md[j] > bv) { bv = md[j]; bi = i; }   // strict >: lowest idx wins
        }
        unsigned key  = __float_as_uint(bv);
        unsigned vmax = __reduce_max_sync(0xffffffffu, key);
        unsigned cand = (key == vmax) ? (unsigned)bi : 0xffffffffu;
        unsigned imin = __reduce_min_sync(0xffffffffu, cand);
        int buf = s & 1;
        if (lane == 0) { svk[buf*4 + w] = vmax; svi[buf*4 + w] = imin; }
        __syncthreads();
        unsigned k2 = (lane < 4) ? svk[buf*4 + lane] : 0u;
        unsigned i2 = (lane < 4) ? svi[buf*4 + lane] : 0xffffffffu;
        unsigned vm2 = __reduce_max_sync(0xffffffffu, k2);
        unsigned c2  = (k2 == vm2) ? i2 : 0xffffffffu;
        last = (int)__reduce_min_sync(0xffffffffu, c2);
        if (((s & 15) == 15) && t == 0) {
            __threadfence();
            *((volatile int*)&g_prog[b]) = s + 1;
        }
    }
    if (t == 0) {
        __threadfence();
        *((volatile int*)&g_prog[b]) = SS;
    }
}

// --- inline radius-capped kNN for one centroid; results -> nlist (smem) + g_cnt ---
__device__ void nbr_one(float* scr, int* nlist, int* cnt_out, int cc, int t) {
    float* sd   = scr;                       // 1024
    int*   sid  = (int*)(scr + 1024);        // 1024
    int*   hist = (int*)(scr + 2048);        // 128
    float* td   = scr + 2176;                // 256
    int*   tdi  = (int*)(scr + 2432);        // 256
    int*   wtot = (int*)(scr + 2688);        // 4
    int*   scal = (int*)(scr + 2692);        // sc, so, s_tb, s_m, tc
    int b = cc >> 11;
    if (t == 0) { scal[0] = 0; scal[1] = 0; scal[4] = 0; }
    hist[t] = 0;
    float cx = __ldcg(&g_ctr[cc*3]);
    float cy = __ldcg(&g_ctr[cc*3+1]);
    float cz = __ldcg(&g_ctr[cc*3+2]);
    __syncthreads();
    for (int i = t; i < NPTS; i += 128) {
        float4 P = g_pos4[b*NPTS + i];
        float dx = P.x-cx, dy = P.y-cy, dz = P.z-cz;
        float d = fmaf(dz, dz, fmaf(dy, dy, __fmul_rn(dx, dx)));
        if (d <= R2F) {
            int k = atomicAdd(&scal[0], 1);
            if (k < MAXC) { sd[k] = d; sid[k] = i; }
        }
    }
    __syncthreads();
    int cnt = min(scal[0], MAXC);
    if (cnt <= KNB) {
        if (t < cnt) nlist[t] = sid[t];
        if (t == 0) { *cnt_out = cnt; g_cnt[cc] = cnt; }
        __syncthreads();
        return;
    }
    const float bsc = 128.0f / R2F;
    for (int i = t; i < cnt; i += 128) {
        int bk = min(127, (int)(sd[i] * bsc));
        atomicAdd(&hist[bk], 1);
    }
    __syncthreads();
    {
        int lane = t & 31, w = t >> 5;
        int h = hist[t], v = h;
#pragma unroll
        for (int o = 1; o < 32; o <<= 1) {
            int u = __shfl_up_sync(0xffffffffu, v, o);
            if (lane >= o) v += u;
        }
        if (lane == 31) wtot[w] = v;
        __syncthreads();
        int base = 0;
        for (int k2 = 0; k2 < w; k2++) base += wtot[k2];
        int incl = v + base, excl = incl - h;
        if (incl >= KNB && excl < KNB) { scal[2] = t; scal[3] = excl; }
    }
    __syncthreads();
    int tb = scal[2], m = scal[3];
    for (int i = t; i < cnt; i += 128) {
        int bk = min(127, (int)(sd[i] * bsc));
        if (bk < tb) {
            int k = atomicAdd(&scal[1], 1);
            nlist[k] = sid[i];
        } else if (bk == tb) {
            int k = atomicAdd(&scal[4], 1);
            if (k < 256) { td[k] = sd[i]; tdi[k] = sid[i]; }
        }
    }
    __syncthreads();
    int bn = min(scal[4], 256), rem = KNB - m;
    for (int i = t; i < bn; i += 128) {
        float di = td[i]; int ii = tdi[i];
        int rank = 0;
        for (int j2 = 0; j2 < bn; j2++) {
            float dj = td[j2]; int ij = tdi[j2];
            if (dj < di || (dj == di && ij < ii)) rank++;
        }
        if (rank < rem) {
            int k = atomicAdd(&scal[1], 1);
            nlist[k] = tdi[i];
        }
    }
    if (t == 0) { *cnt_out = KNB; g_cnt[cc] = KNB; }
    __syncthreads();
}

__global__ void __launch_bounds__(128, 2)
k_fuse(const float* __restrict__ x, const float* __restrict__ b0,
       float* __restrict__ octr, float* __restrict__ obat) {
    extern __shared__ float sm[];
    int bid = blockIdx.x, t = threadIdx.x;
    if (bid < BB) { fps_role(sm, bid, t, octr, obat); return; }

    // ---- l0 role: blk owns centroids 2blk, 2blk+1 ----
    int blk = bid - BB;
    float*    sA    = sm;                          // 128*132 f32 (also nbr scratch)
    uint32_t* sB0   = (uint32_t*)(sm + 128*SROW);  // 4096 u32
    uint32_t* sB1   = sB0 + 4096;
    float*    bias  = sm + 128*SROW + 8192;        // 128
    int*      nlist = (int*)(bias + 128);          // 128 ints
    int*      cnt2  = nlist + 128;                 // 2 ints
    int w = t >> 5, lane = t & 31;
    bias[t] = b0[t];
    stageB(sB0, g_WF0, t);      // W0 slab 0 in flight

    // neighbor search for both centroids (spin on fps progress)
#pragma unroll 1
    for (int half = 0; half < 2; half++) {
        int cc = 2*blk + half;
        int b = cc >> 11, sIdx = cc & 2047;
        if (t == 0) {
            while (*((volatile int*)&g_prog[b]) <= sIdx) __nanosleep(128);
        }
        __syncthreads();
        __threadfence();
        nbr_one(sA, nlist + half*KNB, cnt2 + half, cc, t);
    }
    __syncthreads();

    // gather: row t = edge; read nlist/cnt2 from smem
    int c2 = 2*blk + (t >> 6), e = t & 63;
    int cnt_my = cnt2[t >> 6];
    int jn = nlist[t];
    float* row = sA + t*SROW;   // overwrites nbr scratch (all reads done)
    __syncthreads();            // everyone got nlist/cnt before sA overwrite
    float4 z4 = make_float4(0.f, 0.f, 0.f, 0.f);
    if (e < cnt_my) {
        int bcl = c2 >> 11;
        const float4* xr = (const float4*)(x + (size_t)(bcl*NPTS + jn)*CIN);
#pragma unroll
        for (int q = 0; q < 16; q++)
            *(float4*)(row + 4*q) = xr[q];
        float4 P = g_pos4[bcl*NPTS + jn];
        row[64] = P.x - __ldcg(&g_ctr[c2*3]);
        row[65] = P.y - __ldcg(&g_ctr[c2*3+1]);
        row[66] = P.z - __ldcg(&g_ctr[c2*3+2]);
        row[67] = 0.f;
        *(float4*)(row + 68) = z4;
        *(float4*)(row + 72) = z4;
        *(float4*)(row + 76) = z4;
    } else {
#pragma unroll
        for (int q = 0; q < 20; q++)
            *(float4*)(row + 4*q) = z4;
    }

    float acc[32][4];
#pragma unroll
    for (int i = 0; i < 32; i++)
#pragma unroll
        for (int r = 0; r < 4; r++) acc[i][r] = 0.f;

    uint32_t* bufs[2] = { sB0, sB1 };
#pragma unroll 1
    for (int s = 0; s < 3; s++) {
        CP_WAIT0();
        __syncthreads();
        if (s + 1 < 3) stageB(bufs[(s+1)&1], g_WF0 + (s+1)*4096, t);
        gemm_slab(sA, bufs[s&1], acc, w, lane, s*32, (s < 2) ? 2 : 1);
    }

    epi_to_stage(sA, acc, bias, w, lane);
    __syncthreads();

    stage_to_H(g_H0h + (size_t)blk * 4096, sA, t);

    int cnt0 = cnt2[0], cnt1 = cnt2[1];
    float ssum = 0.f, ssq = 0.f;
    for (int r = 0; r < 128; r++) {
        bool val = (r & 63) < ((r >> 6) ? cnt1 : cnt0);
        float v = sA[r*SROW + t];
        if (val) { ssum += v; ssq = fmaf(v, v, ssq); }
    }
    atomicAdd(&g_stat[0][0][blk & 31][t], (double)ssum);
    atomicAdd(&g_stat[0][1][blk & 31][t], (double)ssq);
}

// ---------------- bn prepare ----------------
__global__ void k_prep(const float* __restrict__ gamma,
                       const float* __restrict__ beta, int layer) {
    int t = threadIdx.x;
    int local = 0;
    for (int i = t; i < BSZ; i += 128) local += g_cnt[i];
    __shared__ int sred[4];
    int lane = t & 31, w = t >> 5;
#pragma unroll
    for (int off = 16; off > 0; off >>= 1)
        local += __shfl_down_sync(0xffffffffu, local, off);
    if (lane == 0) sred[w] = local;
    __syncthreads();
    double cntd = (double)(sred[0] + sred[1] + sred[2] + sred[3]);
    double s = 0.0, q = 0.0;
    for (int k = 0; k < 32; k++) {
        s += g_stat[layer][0][k][t];
        q += g_stat[layer][1][k][t];
    }
    double mean = s / cntd;
    double var = q / cntd - mean * mean;
    if (var < 0.0) var = 0.0;
    double a = (double)gamma[t] * rsqrt(var + 1e-5);
    g_scale[layer][t] = (float)a;
    g_shift[layer][t] = (float)((double)beta[t] - mean * a);
}

// ---------------- layer 1 (R14, M=128) ----------------
__global__ void __launch_bounds__(128, 2) k_l1(const float* __restrict__ b1) {
    extern __shared__ float sm[];
    float*    sA   = sm;
    uint32_t* sB0  = (uint32_t*)(sm + 128*SROW);
    uint32_t* sB1  = sB0 + 4096;
    float*    bias = sm + 128*SROW + 8192;
    float*    sc   = bias + 128;
    float*    sh   = sc + 128;
    int t = threadIdx.x, w = t >> 5, lane = t & 31, blk = blockIdx.x;
    bias[t] = b1[t]; sc[t] = g_scale[0][t]; sh[t] = g_shift[0][t];

    stageB(sB0, g_WF1, t);
    __syncthreads();

    H_to_stage(sA, g_H0h + (size_t)blk * 4096, t, sc, sh);

    float acc[32][4];
#pragma unroll
    for (int i = 0; i < 32; i++)
#pragma unroll
        for (int r = 0; r < 4; r++) acc[i][r] = 0.f;

    uint32_t* bufs[2] = { sB0, sB1 };
#pragma unroll 1
    for (int s = 0; s < 4; s++) {
        CP_WAIT0();
        __syncthreads();
        if (s + 1 < 4) stageB(bufs[(s+1)&1], g_WF1 + (s+1)*4096, t);
        gemm_slab(sA, bufs[s&1], acc, w, lane, s*32, 2);
    }

    epi_to_stage(sA, acc, bias, w, lane);
    __syncthreads();

    stage_to_H(g_H1h + (size_t)blk * 4096, sA, t);

    int cnt0 = g_cnt[blk*2], cnt1 = g_cnt[blk*2+1];
    float ssum = 0.f, ssq = 0.f;
    for (int r = 0; r < 128; r++) {
        bool val = (r & 63) < ((r >> 6) ? cnt1 : cnt0);
        float v = sA[r*SROW + t];
        if (val) { ssum += v; ssq = fmaf(v, v, ssq); }
    }
    atomicAdd(&g_stat[1][0][blk & 31][t], (double)ssum);
    atomicAdd(&g_stat[1][1][blk & 31][t], (double)ssq);
}

// ---------------- layer 2 (R14, M=128) ----------------
__global__ void __launch_bounds__(128, 2) k_l2(const float* __restrict__ b2,
                                               float* __restrict__ outp) {
    extern __shared__ float sm[];
    float*    sA   = sm;
    uint32_t* sB0  = (uint32_t*)(sm + 128*SROW);
    uint32_t* sB1  = sB0 + 4096;
    float*    bias = sm + 128*SROW + 8192;
    float*    sc   = bias + 128;
    float*    sh   = sc + 128;
    int t = threadIdx.x, w = t >> 5, lane = t & 31, blk = blockIdx.x;
    bias[t] = b2[t]; sc[t] = g_scale[1][t]; sh[t] = g_shift[1][t];

    stageB(sB0, g_WF2, t);
    __syncthreads();

    H_to_stage(sA, g_H1h + (size_t)blk * 4096, t, sc, sh);

    float acc[32][4];
#pragma unroll
    for (int i = 0; i < 32; i++)
#pragma unroll
        for (int r = 0; r < 4; r++) acc[i][r] = 0.f;

    uint32_t* bufs[2] = { sB0, sB1 };
#pragma unroll 1
    for (int s = 0; s < 4; s++) {
        CP_WAIT0();
        __syncthreads();
        if (s + 1 < 4) stageB(bufs[(s+1)&1], g_WF2 + (s+1)*4096, t);
        gemm_slab(sA, bufs[s&1], acc, w, lane, s*32, 2);
    }

    epi_to_stage(sA, acc, bias, w, lane);
    __syncthreads();

    int cnt0 = g_cnt[blk*2], cnt1 = g_cnt[blk*2+1];
    const float NINF = __int_as_float(0xff800000);
    float m0 = NINF, m1 = NINF;
    for (int r = 0; r < 64; r++)
        if (r < cnt0) m0 = fmaxf(m0, sA[r*SROW + t]);
    for (int r = 64; r < 128; r++)
        if ((r - 64) < cnt1) m1 = fmaxf(m1, sA[r*SROW + t]);
    outp[(size_t)(blk*2)     * HID + t] = m0;
    outp[(size_t)(blk*2 + 1) * HID + t] = m1;
}

// ---------------- launch ----------------
extern "C" void kernel_launch(void* const* d_in, const int* in_sizes, int n_in,
                              void* d_out, int out_size) {
    const float* x   = (const float*)d_in[0];
    const float* pos = (const float*)d_in[1];
    const float* W0  = (const float*)d_in[3];
    const float* b0  = (const float*)d_in[4];
    const float* g0  = (const float*)d_in[5];
    const float* be0 = (const float*)d_in[6];
    const float* W1  = (const float*)d_in[7];
    const float* b1  = (const float*)d_in[8];
    const float* g1  = (const float*)d_in[9];
    const float* be1 = (const float*)d_in[10];
    const float* W2  = (const float*)d_in[11];
    const float* b2  = (const float*)d_in[12];
    float* out = (float*)d_out;

    float* octr = (out_size >= BSZ*HID + BSZ*3) ? out + (size_t)BSZ*HID : nullptr;
    float* obat = (out_size >= BSZ*HID + BSZ*3 + BSZ) ? out + (size_t)BSZ*131 : nullptr;

    int smB = (128*SROW + 8192 + 384 + 132) * 4;   // +nlist/cnt2: 102,416 B
    cudaFuncSetAttribute(k_fuse, cudaFuncAttributeMaxDynamicSharedMemorySize, smB);
    cudaFuncSetAttribute(k_l1,  cudaFuncAttributeMaxDynamicSharedMemorySize, smB);
    cudaFuncSetAttribute(k_l2,  cudaFuncAttributeMaxDynamicSharedMemorySize, smB);

    // k_fuse is launch #4 -> ncu capture slot
    k_pA<<<(49160 + 255)/256, 256>>>(pos);
    k_pB<<<(14336 + 255)/256, 256>>>(W0, W1);
    k_pC<<<(8192 + 255)/256, 256>>>(W2);
    k_fuse<<<BB + NBLK, 128, smB>>>(x, b0, octr, obat);
    k_prep<<<1, 128>>>(g0, be0, 0);
    k_l1<<<NBLK, 128, smB>>>(b1);
    k_prep<<<1, 128>>>(g1, be1, 1);
    k_l2<<<NBLK, 128, smB>>>(b2, out);
}